// round 4
// baseline (speedup 1.0000x reference)
#include <cuda_runtime.h>
#include <stdint.h>

#define NUM_FIELDS 10
#define VOCAB      100000
#define EMBED      16            // floats per embedding row (64 bytes)
#define BATCH      16384
#define NPAIRS     45            // C(10,2)

// triu_indices(10, k=1): pair p -> (ii[p], jj[p]) with ii < jj
__constant__ unsigned char c_ii[NPAIRS] = {
    0,0,0,0,0,0,0,0,0,
    1,1,1,1,1,1,1,1,
    2,2,2,2,2,2,2,
    3,3,3,3,3,3,
    4,4,4,4,4,
    5,5,5,5,
    6,6,6,
    7,7,
    8
};
__constant__ unsigned char c_jj[NPAIRS] = {
    1,2,3,4,5,6,7,8,9,
    2,3,4,5,6,7,8,9,
    3,4,5,6,7,8,9,
    4,5,6,7,8,9,
    5,6,7,8,9,
    6,7,8,9,
    7,8,9,
    8,9,
    9
};

// 4 lanes per (batch, pair): lane q loads float4 q of rowA and rowB.
// Gathers use DEFAULT cache policy: the ~85MB distinct-row working set is
// identical on every graph replay and fits in the 126MB L2 -> let it stay
// resident. Output uses evict-first stores so the 47MB write stream does
// not displace the resident gather set.
__global__ __launch_bounds__(256)
void ffm_kernel(const int*    __restrict__ x,      // int32 (16384, 10)
                const float4* __restrict__ emb,    // (10, 1e6, 16) as float4[40M]
                float4*       __restrict__ out)    // (16384, 45, 16) as float4
{
    int gid = blockIdx.x * blockDim.x + threadIdx.x;
    if (gid >= BATCH * NPAIRS * 4) return;

    int q = gid & 3;          // which float4 of the row
    int e = gid >> 2;         // linear (b, pair)
    int b = e / NPAIRS;
    int p = e - b * NPAIRS;
    int i = c_ii[p];
    int j = c_jj[p];

    // 4 lanes of a quad read the same address -> broadcast
    int xi = x[b * NUM_FIELDS + i];
    int xj = x[b * NUM_FIELDS + j];
    xi = min(max(xi, 0), VOCAB - 1);
    xj = min(max(xj, 0), VOCAB - 1);

    // out[b,p] = emb[j, x[b,i]+i*V] * emb[i, x[b,j]+j*V]
    size_t rowA = (size_t)j * (NUM_FIELDS * (size_t)VOCAB) + (size_t)xi + (size_t)i * VOCAB;
    size_t rowB = (size_t)i * (NUM_FIELDS * (size_t)VOCAB) + (size_t)xj + (size_t)j * VOCAB;

    // Default (evict-normal) loads: keep the replayed gather set L2-resident.
    float4 a = __ldg(emb + rowA * (EMBED / 4) + q);
    float4 v = __ldg(emb + rowB * (EMBED / 4) + q);

    float4 o;
    o.x = a.x * v.x;
    o.y = a.y * v.y;
    o.z = a.z * v.z;
    o.w = a.w * v.w;

    // Evict-first stores: stream the output through L2 without thrashing it.
    __stcs(out + (size_t)e * (EMBED / 4) + q, o);
}

extern "C" void kernel_launch(void* const* d_in, const int* in_sizes, int n_in,
                              void* d_out, int out_size)
{
    const int*    x   = (const int*)d_in[0];      // indices (int32 on device)
    const float4* emb = (const float4*)d_in[1];   // float32 (10, 1e6, 16)
    float4*       out = (float4*)d_out;           // float32 (16384, 45, 16)

    const int total = BATCH * NPAIRS * 4;         // 2,949,120 threads
    const int block = 256;
    const int grid  = (total + block - 1) / block;
    ffm_kernel<<<grid, block>>>(x, emb, out);
}

// round 5
// speedup vs baseline: 1.0512x; 1.0512x over previous
#include <cuda_runtime.h>
#include <stdint.h>

#define NUM_FIELDS 10
#define VOCAB      100000
#define EMBED      16            // floats per embedding row (64 bytes)
#define BATCH      16384
#define NPAIRS     45            // C(10,2)

// triu_indices(10, k=1): pair p -> (ii[p], jj[p]) with ii < jj
__constant__ unsigned char c_ii[NPAIRS] = {
    0,0,0,0,0,0,0,0,0,
    1,1,1,1,1,1,1,1,
    2,2,2,2,2,2,2,
    3,3,3,3,3,3,
    4,4,4,4,4,
    5,5,5,5,
    6,6,6,
    7,7,
    8
};
__constant__ unsigned char c_jj[NPAIRS] = {
    1,2,3,4,5,6,7,8,9,
    2,3,4,5,6,7,8,9,
    3,4,5,6,7,8,9,
    4,5,6,7,8,9,
    5,6,7,8,9,
    6,7,8,9,
    7,8,9,
    8,9,
    9
};

// 4 lanes per (batch, pair): lane q loads float4 q of rowA and rowB.
//   gathers: __ldcs streaming (no reuse; R3-proven best)
//   stores:  __stwt write-through, NO L2 allocation -> eliminates any
//            fetch-on-write fill of output lines (suspected +47MB DRAM reads)
__global__ __launch_bounds__(256)
void ffm_kernel(const int*    __restrict__ x,      // int32 (16384, 10)
                const float4* __restrict__ emb,    // (10, 1e6, 16) as float4[40M]
                float4*       __restrict__ out)    // (16384, 45, 16) as float4
{
    int gid = blockIdx.x * blockDim.x + threadIdx.x;
    if (gid >= BATCH * NPAIRS * 4) return;

    int q = gid & 3;          // which float4 of the row
    int e = gid >> 2;         // linear (b, pair)
    int b = e / NPAIRS;
    int p = e - b * NPAIRS;
    int i = c_ii[p];
    int j = c_jj[p];

    // 4 lanes of a quad read the same address -> broadcast
    int xi = x[b * NUM_FIELDS + i];
    int xj = x[b * NUM_FIELDS + j];
    xi = min(max(xi, 0), VOCAB - 1);
    xj = min(max(xj, 0), VOCAB - 1);

    // out[b,p] = emb[j, x[b,i]+i*V] * emb[i, x[b,j]+j*V]
    size_t rowA = (size_t)j * (NUM_FIELDS * (size_t)VOCAB) + (size_t)xi + (size_t)i * VOCAB;
    size_t rowB = (size_t)i * (NUM_FIELDS * (size_t)VOCAB) + (size_t)xj + (size_t)j * VOCAB;

    // Streaming loads: rows are used exactly once.
    float4 a = __ldcs(emb + rowA * (EMBED / 4) + q);
    float4 v = __ldcs(emb + rowB * (EMBED / 4) + q);

    float4 o;
    o.x = a.x * v.x;
    o.y = a.y * v.y;
    o.z = a.z * v.z;
    o.w = a.w * v.w;

    // Write-through, no allocate: output is never read back, skip L2 fill.
    __stwt(out + (size_t)e * (EMBED / 4) + q, o);
}

extern "C" void kernel_launch(void* const* d_in, const int* in_sizes, int n_in,
                              void* d_out, int out_size)
{
    const int*    x   = (const int*)d_in[0];      // indices (int32 on device)
    const float4* emb = (const float4*)d_in[1];   // float32 (10, 1e6, 16)
    float4*       out = (float4*)d_out;           // float32 (16384, 45, 16)

    const int total = BATCH * NPAIRS * 4;         // 2,949,120 threads
    const int block = 256;
    const int grid  = (total + block - 1) / block;
    ffm_kernel<<<grid, block>>>(x, emb, out);
}

// round 6
// speedup vs baseline: 1.3150x; 1.2510x over previous
#include <cuda_runtime.h>
#include <stdint.h>

#define NUM_FIELDS 10
#define VOCAB      100000
#define EMBED      16            // floats per embedding row (64 bytes)
#define BATCH      16384
#define NPAIRS     45            // C(10,2)
#define B_PER_BLK  64            // quads per 256-thread block

// triu_indices(10, k=1): pair p -> (ii[p], jj[p]) with ii < jj
__constant__ unsigned char c_ii[NPAIRS] = {
    0,0,0,0,0,0,0,0,0,
    1,1,1,1,1,1,1,1,
    2,2,2,2,2,2,2,
    3,3,3,3,3,3,
    4,4,4,4,4,
    5,5,5,5,
    6,6,6,
    7,7,
    8
};
__constant__ unsigned char c_jj[NPAIRS] = {
    1,2,3,4,5,6,7,8,9,
    2,3,4,5,6,7,8,9,
    3,4,5,6,7,8,9,
    4,5,6,7,8,9,
    5,6,7,8,9,
    6,7,8,9,
    7,8,9,
    8,9,
    9
};

// PAIR-MAJOR grid: blockIdx.y = pair slot, blockIdx.x = 64-wide b tile.
// At any instant the resident CTAs cover only ~5 pair slots -> the live
// gather footprint shrinks from 2.5GB to ~60MB (2 x 6.4MB regions per slot),
// concentrating DRAM row/bank locality and making hot pages TLB-resident.
// 4 lanes per (b,p): lane q handles float4 q of both rows (coalesced 64B).
__global__ __launch_bounds__(256)
void ffm_kernel(const int*    __restrict__ x,      // int32 (16384, 10)
                const float4* __restrict__ emb,    // (10, 1e6, 16) as float4[40M]
                float4*       __restrict__ out)    // (16384, 45, 16) as float4
{
    int q    = threadIdx.x & 3;
    int quad = threadIdx.x >> 2;                   // 0..63
    int b    = blockIdx.x * B_PER_BLK + quad;      // exact fit: 256*64 = 16384
    int p    = blockIdx.y;                         // uniform per block
    int i    = c_ii[p];
    int j    = c_jj[p];

    // broadcast within quad; ~3 cache lines per warp (stride-40B over 8 b's)
    int xi = x[b * NUM_FIELDS + i];
    int xj = x[b * NUM_FIELDS + j];
    xi = min(max(xi, 0), VOCAB - 1);
    xj = min(max(xj, 0), VOCAB - 1);

    // out[b,p] = emb[j, x[b,i]+i*V] * emb[i, x[b,j]+j*V]
    size_t rowA = (size_t)j * (NUM_FIELDS * (size_t)VOCAB) + (size_t)xi + (size_t)i * VOCAB;
    size_t rowB = (size_t)i * (NUM_FIELDS * (size_t)VOCAB) + (size_t)xj + (size_t)j * VOCAB;

    // Streaming loads: rows are used exactly once.
    float4 a = __ldcs(emb + rowA * (EMBED / 4) + q);
    float4 v = __ldcs(emb + rowB * (EMBED / 4) + q);

    float4 o;
    o.x = a.x * v.x;
    o.y = a.y * v.y;
    o.z = a.z * v.z;
    o.w = a.w * v.w;

    // 64B sector-complete chunk at stride 2880B; evict-first write-back.
    __stcs(out + ((size_t)b * NPAIRS + p) * (EMBED / 4) + q, o);
}

extern "C" void kernel_launch(void* const* d_in, const int* in_sizes, int n_in,
                              void* d_out, int out_size)
{
    const int*    x   = (const int*)d_in[0];      // indices (int32 on device)
    const float4* emb = (const float4*)d_in[1];   // float32 (10, 1e6, 16)
    float4*       out = (float4*)d_out;           // float32 (16384, 45, 16)

    dim3 grid(BATCH / B_PER_BLK, NPAIRS);         // (256, 45)
    ffm_kernel<<<grid, 256>>>(x, emb, out);
}